// round 16
// baseline (speedup 1.0000x reference)
#include <cuda_runtime.h>
#include <cuda_bf16.h>
#include <math.h>
#include <stdint.h>

// ---------------- problem constants ----------------
#define B_    8
#define L_    8192
#define DM    256
#define DI    512
#define DS    4
#define DTR   16
#define NPROJ 24          // DTR + 2*DS
#define M_    (B_*L_)     // 65536

// ---------------- scratch (static device globals; no runtime alloc) --------
__device__ float g_xz[(size_t)M_ * 1024];   // [m][1024]: xm=[0,512), z=[512,1024). reused for h64 later
__device__ float g_dt[(size_t)M_ * DI];     // softplus(dt)
__device__ float g_bc[(size_t)M_ * 8];      // per (b,l): B[4], C[4]
__device__ float g_y512[(size_t)M_ * DI];   // scan output, gated
__device__ float g_y256[(size_t)M_ * DM];   // after out_proj
__device__ float g_logit[(size_t)M_];
__device__ float g_red[B_ * 2];             // per batch: max, sumexp
__device__ float g_part[32 * B_ * DM];      // partial weighted sums

// ===================== tensor-core GEMM (bf16 split-3) ======================
#define LDA 40        // smem row stride in bf16 (32 + 8 pad) -> conflict-free ldmatrix

__device__ __forceinline__ unsigned sptr(const void* p) {
    return (unsigned)__cvta_generic_to_shared(p);
}
__device__ __forceinline__ void ldm4(unsigned addr, uint32_t& r0, uint32_t& r1,
                                     uint32_t& r2, uint32_t& r3) {
    asm volatile("ldmatrix.sync.aligned.m8n8.x4.shared.b16 {%0,%1,%2,%3}, [%4];"
                 : "=r"(r0), "=r"(r1), "=r"(r2), "=r"(r3) : "r"(addr));
}
__device__ __forceinline__ void mma_bf16(float* d, const uint32_t* a, const uint32_t* b) {
    asm volatile(
        "mma.sync.aligned.m16n8k16.row.col.f32.bf16.bf16.f32 "
        "{%0,%1,%2,%3},{%4,%5,%6,%7},{%8,%9},{%0,%1,%2,%3};"
        : "+f"(d[0]), "+f"(d[1]), "+f"(d[2]), "+f"(d[3])
        : "r"(a[0]), "r"(a[1]), "r"(a[2]), "r"(a[3]), "r"(b[0]), "r"(b[1]));
}
__device__ __forceinline__ uint32_t pk(__nv_bfloat16 a, __nv_bfloat16 b) {
    __nv_bfloat162 t; t.x = a; t.y = b;
    return *reinterpret_cast<uint32_t*>(&t);
}
__device__ __forceinline__ void cvt4(float4 v, uint32_t& h01, uint32_t& h23,
                                     uint32_t& l01, uint32_t& l23) {
    __nv_bfloat16 h0 = __float2bfloat16_rn(v.x);
    __nv_bfloat16 h1 = __float2bfloat16_rn(v.y);
    __nv_bfloat16 h2 = __float2bfloat16_rn(v.z);
    __nv_bfloat16 h3 = __float2bfloat16_rn(v.w);
    __nv_bfloat16 l0 = __float2bfloat16_rn(v.x - __bfloat162float(h0));
    __nv_bfloat16 l1 = __float2bfloat16_rn(v.y - __bfloat162float(h1));
    __nv_bfloat16 l2 = __float2bfloat16_rn(v.z - __bfloat162float(h2));
    __nv_bfloat16 l3 = __float2bfloat16_rn(v.w - __bfloat162float(h3));
    h01 = pk(h0, h1); h23 = pk(h2, h3);
    l01 = pk(l0, l1); l23 = pk(l2, l3);
}

// BM=128, BN=128, BK=32, 256 threads = 8 warps (2 x 4), warp tile 64x32
__global__ void __launch_bounds__(256, 1) gemm_mma(
        const float* __restrict__ A, const float* __restrict__ W,
        float* __restrict__ C, int M, int N, int K) {
    __shared__ __align__(16) __nv_bfloat16 sAh[128 * LDA];
    __shared__ __align__(16) __nv_bfloat16 sAl[128 * LDA];
    __shared__ __align__(16) __nv_bfloat16 sWh[128 * LDA];
    __shared__ __align__(16) __nv_bfloat16 sWl[128 * LDA];

    const int tid  = threadIdx.x;
    const int lane = tid & 31;
    const int warp = tid >> 5;
    const int wm = warp >> 2;
    const int wn = warp & 3;
    const long rowBase = (long)blockIdx.y * 128;
    const long colBase = (long)blockIdx.x * 128;
    const int nT = K >> 5;

    float acc[4][4][4];
#pragma unroll
    for (int i = 0; i < 4; i++)
#pragma unroll
        for (int j = 0; j < 4; j++)
#pragma unroll
            for (int q = 0; q < 4; q++) acc[i][j][q] = 0.f;

    float4 aR[4], wR[4];

#pragma unroll
    for (int i = 0; i < 4; i++) {
        int idx = tid + i * 256, r = idx >> 3, kq = idx & 7;
        aR[i] = *(const float4*)&A[(rowBase + r) * K + kq * 4];
        wR[i] = *(const float4*)&W[(colBase + r) * K + kq * 4];
    }

    const int rA = lane & 7, tA = lane >> 3;
    const int aRowOff = ((tA & 1) << 3) + rA;
    const int aKOff   = (tA >> 1) << 3;
    const int bNOff   = ((tA >> 1) << 3) + rA;
    const int bKOff   = (tA & 1) << 3;

    for (int t = 0;;) {
#pragma unroll
        for (int i = 0; i < 4; i++) {
            int idx = tid + i * 256, r = idx >> 3, kq = idx & 7;
            uint32_t h01, h23, l01, l23;
            cvt4(aR[i], h01, h23, l01, l23);
            *(uint2*)&sAh[r * LDA + kq * 4] = make_uint2(h01, h23);
            *(uint2*)&sAl[r * LDA + kq * 4] = make_uint2(l01, l23);
            cvt4(wR[i], h01, h23, l01, l23);
            *(uint2*)&sWh[r * LDA + kq * 4] = make_uint2(h01, h23);
            *(uint2*)&sWl[r * LDA + kq * 4] = make_uint2(l01, l23);
        }
        __syncthreads();

        if (t + 1 < nT) {
#pragma unroll
            for (int i = 0; i < 4; i++) {
                int idx = tid + i * 256, r = idx >> 3, kq = idx & 7;
                aR[i] = *(const float4*)&A[(rowBase + r) * K + (t + 1) * 32 + kq * 4];
                wR[i] = *(const float4*)&W[(colBase + r) * K + (t + 1) * 32 + kq * 4];
            }
        }

#pragma unroll
        for (int ks = 0; ks < 2; ks++) {
            const int k0 = ks * 16;
            uint32_t Ah[4][4], Al[4][4], Bh[4][2], Bl[4][2];
#pragma unroll
            for (int mt = 0; mt < 4; mt++) {
                int rr = wm * 64 + mt * 16 + aRowOff;
                int kc = k0 + aKOff;
                ldm4(sptr(&sAh[rr * LDA + kc]), Ah[mt][0], Ah[mt][1], Ah[mt][2], Ah[mt][3]);
                ldm4(sptr(&sAl[rr * LDA + kc]), Al[mt][0], Al[mt][1], Al[mt][2], Al[mt][3]);
            }
#pragma unroll
            for (int np = 0; np < 2; np++) {
                int nn = wn * 32 + np * 16 + bNOff;
                int kc = k0 + bKOff;
                ldm4(sptr(&sWh[nn * LDA + kc]),
                     Bh[2 * np][0], Bh[2 * np][1], Bh[2 * np + 1][0], Bh[2 * np + 1][1]);
                ldm4(sptr(&sWl[nn * LDA + kc]),
                     Bl[2 * np][0], Bl[2 * np][1], Bl[2 * np + 1][0], Bl[2 * np + 1][1]);
            }
#pragma unroll
            for (int mt = 0; mt < 4; mt++)
#pragma unroll
                for (int nf = 0; nf < 4; nf++) {
                    mma_bf16(acc[mt][nf], Ah[mt], Bh[nf]);
                    mma_bf16(acc[mt][nf], Ah[mt], Bl[nf]);
                    mma_bf16(acc[mt][nf], Al[mt], Bh[nf]);
                }
        }
        __syncthreads();
        if (++t == nT) break;
    }

#pragma unroll
    for (int mt = 0; mt < 4; mt++) {
        long row = rowBase + wm * 64 + mt * 16 + (lane >> 2);
#pragma unroll
        for (int nf = 0; nf < 4; nf++) {
            long col = colBase + wn * 32 + nf * 8 + ((lane & 3) << 1);
            *(float2*)&C[row * N + col] = make_float2(acc[mt][nf][0], acc[mt][nf][1]);
            *(float2*)&C[(row + 8) * N + col] = make_float2(acc[mt][nf][2], acc[mt][nf][3]);
        }
    }
}

// ---------------- fp32 SIMT GEMM (kept for the small MLP layer-1) ----------
template<int BM, int BN, int BK, int TM, int TN>
__global__ void __launch_bounds__((BM/TM)*(BN/TN)) gemm_tn(
        const float* __restrict__ A, const float* __restrict__ W,
        float* __restrict__ C, int M, int N, int K) {
    constexpr int NT = (BM / TM) * (BN / TN);
    constexpr int A4 = BM * BK / 4;
    constexpr int W4 = BN * BK / 4;
    constexpr int KQ = BK / 4;
    constexpr int AperT = (A4 + NT - 1) / NT;
    constexpr int WperT = (W4 + NT - 1) / NT;

    __shared__ float As[2][BK][BM + 4];
    __shared__ float Ws[2][BK][BN + 4];

    const int tid = threadIdx.x;
    const int tx = tid % (BN / TN);
    const int ty = tid / (BN / TN);
    const long rowBase = (long)blockIdx.y * BM;
    const int  colBase = blockIdx.x * BN;

    float acc[TM][TN];
#pragma unroll
    for (int i = 0; i < TM; i++)
#pragma unroll
        for (int j = 0; j < TN; j++) acc[i][j] = 0.f;

    float4 aR[AperT], wR[WperT];
    const int nTiles = K / BK;

    auto ldA = [&](int t) {
#pragma unroll
        for (int i = 0; i < AperT; i++) {
            int idx = tid + i * NT;
            if (idx < A4) {
                int row = idx / KQ, kq = idx % KQ;
                aR[i] = *(const float4*)&A[(rowBase + row) * K + t * BK + kq * 4];
            }
        }
    };
    auto ldW = [&](int t) {
#pragma unroll
        for (int i = 0; i < WperT; i++) {
            int idx = tid + i * NT;
            if (idx < W4) {
                int row = idx / KQ, kq = idx % KQ;
                wR[i] = *(const float4*)&W[(long)(colBase + row) * K + t * BK + kq * 4];
            }
        }
    };
    auto stA = [&](int buf) {
#pragma unroll
        for (int i = 0; i < AperT; i++) {
            int idx = tid + i * NT;
            if (idx < A4) {
                int row = idx / KQ, kq = idx % KQ;
                As[buf][kq * 4 + 0][row] = aR[i].x;
                As[buf][kq * 4 + 1][row] = aR[i].y;
                As[buf][kq * 4 + 2][row] = aR[i].z;
                As[buf][kq * 4 + 3][row] = aR[i].w;
            }
        }
    };
    auto stW = [&](int buf) {
#pragma unroll
        for (int i = 0; i < WperT; i++) {
            int idx = tid + i * NT;
            if (idx < W4) {
                int row = idx / KQ, kq = idx % KQ;
                Ws[buf][kq * 4 + 0][row] = wR[i].x;
                Ws[buf][kq * 4 + 1][row] = wR[i].y;
                Ws[buf][kq * 4 + 2][row] = wR[i].z;
                Ws[buf][kq * 4 + 3][row] = wR[i].w;
            }
        }
    };

    ldA(0); ldW(0); stA(0); stW(0);
    __syncthreads();

    for (int t = 0; t < nTiles; t++) {
        const int buf = t & 1;
        if (t + 1 < nTiles) { ldA(t + 1); ldW(t + 1); }
#pragma unroll
        for (int kk = 0; kk < BK; kk++) {
            float a[TM], b[TN];
#pragma unroll
            for (int i = 0; i < TM; i += 4)
                *(float4*)&a[i] = *(const float4*)&As[buf][kk][ty * TM + i];
#pragma unroll
            for (int j = 0; j < TN; j += 4)
                *(float4*)&b[j] = *(const float4*)&Ws[buf][kk][tx * TN + j];
#pragma unroll
            for (int i = 0; i < TM; i++)
#pragma unroll
                for (int j = 0; j < TN; j++)
                    acc[i][j] += a[i] * b[j];
        }
        if (t + 1 < nTiles) { stA(buf ^ 1); stW(buf ^ 1); }
        __syncthreads();
    }

#pragma unroll
    for (int i = 0; i < TM; i++) {
        long row = rowBase + ty * TM + i;
#pragma unroll
        for (int j = 0; j < TN; j += 4) {
            float4 v = make_float4(acc[i][j], acc[i][j + 1], acc[i][j + 2], acc[i][j + 3]);
            *(float4*)&C[row * N + colBase + tx * TN + j] = v;
        }
    }
}

// ---------------- dummy shift kernels (position conv_proj_dt at slot #4) ---
__global__ void dummy_kernel() {
    if (threadIdx.x == 0 && blockIdx.x == 0) g_red[0] = 0.f;   // overwritten later
}

// ---------------- fused conv+silu, x_proj, dt_proj+softplus ---------------
// xc lives only in smem; the scan recomputes conv+silu from g_xz inline.
// x_proj: 4 outputs per pass -> 1 s_xc read feeds 4 FMA chains, 4 interleaved
// shfl reductions (ILP instead of 24 serial reduction chains).
#define RCPD 16
__global__ void __launch_bounds__(256) conv_proj_dt(
        const float* __restrict__ conv_w, const float* __restrict__ conv_b,
        const float* __restrict__ xpw,    // x_proj_w [24,512]
        const float* __restrict__ dtw,    // dt_proj_w [512,16]
        const float* __restrict__ dtb) {
    __shared__ float s_xc[RCPD][DI];
    __shared__ float s_proj[RCPD][NPROJ + 1];
    const int tid = threadIdx.x;
    const size_t mbase = (size_t)blockIdx.x * RCPD;

#pragma unroll
    for (int e = tid; e < RCPD * DI; e += 256) {
        int r = e >> 9, d = e & 511;
        size_t m = mbase + r;
        int l = (int)(m & (L_ - 1));
        float xm = g_xz[m * 1024 + d];
        float xp = (l > 0) ? g_xz[(m - 1) * 1024 + d] : 0.f;
        float v = xm * conv_w[d * 2 + 1] + xp * conv_w[d * 2 + 0] + conv_b[d];
        s_xc[r][d] = __fdividef(v, 1.f + __expf(-v));
    }
    __syncthreads();

    const int w = tid >> 5, lane = tid & 31;
#pragma unroll
    for (int rr = 0; rr < 2; rr++) {
        int r = w * 2 + rr;
#pragma unroll
        for (int j0 = 0; j0 < NPROJ; j0 += 4) {
            float s0 = 0.f, s1 = 0.f, s2 = 0.f, s3 = 0.f;
#pragma unroll 4
            for (int k = lane; k < DI; k += 32) {
                float xv = s_xc[r][k];
                s0 += xv * xpw[(j0 + 0) * DI + k];
                s1 += xv * xpw[(j0 + 1) * DI + k];
                s2 += xv * xpw[(j0 + 2) * DI + k];
                s3 += xv * xpw[(j0 + 3) * DI + k];
            }
#pragma unroll
            for (int o = 16; o > 0; o >>= 1) {
                s0 += __shfl_down_sync(0xffffffffu, s0, o);
                s1 += __shfl_down_sync(0xffffffffu, s1, o);
                s2 += __shfl_down_sync(0xffffffffu, s2, o);
                s3 += __shfl_down_sync(0xffffffffu, s3, o);
            }
            if (lane == 0) {
                s_proj[r][j0 + 0] = s0;
                s_proj[r][j0 + 1] = s1;
                s_proj[r][j0 + 2] = s2;
                s_proj[r][j0 + 3] = s3;
            }
        }
    }
    __syncthreads();

#pragma unroll
    for (int e = tid; e < RCPD * DI; e += 256) {
        int r = e >> 9, d = e & 511;
        float acc = dtb[d];
#pragma unroll
        for (int q = 0; q < DTR; q++) acc += s_proj[r][q] * dtw[d * DTR + q];
        float dt = (acc > 20.f) ? acc : __logf(1.f + __expf(acc));
        g_dt[(mbase + r) * DI + d] = dt;
    }
    if (tid < RCPD * 8) {
        int r = tid >> 3, j = tid & 7;
        g_bc[(mbase + r) * 8 + j] = s_proj[r][16 + j];
    }
}

// ---------------- chunked selective scan + gating (monolithic) -------------
// 256 threads = 16 d-lanes x 16 chunks of 512 steps; grid (DI/16, B_) = 256 blocks.
// 3 blocks/SM resident (20K regs/block). conv+silu inline; x4 unroll, batched loads.
#define NCH 16
__global__ void __launch_bounds__(256) scan_kernel(
        const float* __restrict__ A_log, const float* __restrict__ Dw,
        const float* __restrict__ conv_w, const float* __restrict__ conv_b) {
    __shared__ float sSD[NCH][17];
    __shared__ float sH[4][NCH][17];
    const int tid = threadIdx.x;
    const int dl = tid & 15;
    const int c  = tid >> 4;                 // 0..15
    const int d  = blockIdx.x * 16 + dl;
    const int b  = blockIdx.y;
    const float A0 = -__expf(A_log[d * 4 + 0]);
    const float A1 = -__expf(A_log[d * 4 + 1]);
    const float A2 = -__expf(A_log[d * 4 + 2]);
    const float A3 = -__expf(A_log[d * 4 + 3]);
    const float aA0 = fabsf(A0);
    const bool fast = (fabsf(A1 - 2.f * A0) <= 1e-5f * aA0) &&
                      (fabsf(A2 - 3.f * A0) <= 1e-5f * aA0) &&
                      (fabsf(A3 - 4.f * A0) <= 1e-5f * aA0);
    const float cw0 = conv_w[d * 2], cw1 = conv_w[d * 2 + 1], cb = conv_b[d];
    const int CH = L_ / NCH;                 // 512
    const int l0 = c * CH;
    const size_t baseM = (size_t)b * L_ + l0;

    // ---- pass 1: chunk-local partial state (h_in = 0), track sum(dt) ----
    float xprev = (l0 > 0) ? g_xz[(baseM - 1) * 1024 + d] : 0.f;
    float h0 = 0, h1 = 0, h2 = 0, h3 = 0, sd = 0;
    for (int i = 0; i < CH; i += 4) {
        float dt4[4], xm4[4];
        float4 Bv4[4];
#pragma unroll
        for (int u = 0; u < 4; u++) {         // 12 independent loads in flight
            size_t m = baseM + i + u;
            dt4[u] = g_dt[m * DI + d];
            xm4[u] = g_xz[m * 1024 + d];
            Bv4[u] = *(const float4*)&g_bc[m * 8];
        }
#pragma unroll
        for (int u = 0; u < 4; u++) {
            float v = xm4[u] * cw1 + xprev * cw0 + cb;
            float xv = __fdividef(v, 1.f + __expf(-v));
            xprev = xm4[u];
            float dt = dt4[u];
            float dtx = dt * xv;
            float e1, e2, e3, e4;
            if (fast) { e1 = __expf(dt * A0); e2 = e1 * e1; e3 = e2 * e1; e4 = e2 * e2; }
            else { e1 = __expf(dt * A0); e2 = __expf(dt * A1);
                   e3 = __expf(dt * A2); e4 = __expf(dt * A3); }
            h0 = e1 * h0 + dtx * Bv4[u].x;
            h1 = e2 * h1 + dtx * Bv4[u].y;
            h2 = e3 * h2 + dtx * Bv4[u].z;
            h3 = e4 * h3 + dtx * Bv4[u].w;
            sd += dt;
        }
    }
    sSD[c][dl] = sd;
    sH[0][c][dl] = h0; sH[1][c][dl] = h1; sH[2][c][dl] = h2; sH[3][c][dl] = h3;
    __syncthreads();

    // ---- exclusive combine over the 16 chunks (threads 0..15) ----
    if (tid < 16) {
        float a0 = 0, a1 = 0, a2 = 0, a3 = 0;
        for (int cc = 0; cc < NCH; cc++) {
            float s  = sSD[cc][tid];
            float t0 = sH[0][cc][tid], t1 = sH[1][cc][tid];
            float t2 = sH[2][cc][tid], t3 = sH[3][cc][tid];
            sH[0][cc][tid] = a0; sH[1][cc][tid] = a1;
            sH[2][cc][tid] = a2; sH[3][cc][tid] = a3;
            float e1, e2, e3, e4;
            if (fast) { e1 = __expf(s * A0); e2 = e1 * e1; e3 = e2 * e1; e4 = e2 * e2; }
            else { e1 = __expf(s * A0); e2 = __expf(s * A1);
                   e3 = __expf(s * A2); e4 = __expf(s * A3); }
            a0 = t0 + a0 * e1;
            a1 = t1 + a1 * e2;
            a2 = t2 + a2 * e3;
            a3 = t3 + a3 * e4;
        }
    }
    __syncthreads();

    // ---- pass 2: replay with true h_in, fuse y = (scan + xc*D) * silu(z) ----
    h0 = sH[0][c][dl]; h1 = sH[1][c][dl]; h2 = sH[2][c][dl]; h3 = sH[3][c][dl];
    const float Dd = Dw[d];
    xprev = (l0 > 0) ? g_xz[(baseM - 1) * 1024 + d] : 0.f;
    for (int i = 0; i < CH; i += 4) {
        float dt4[4], xm4[4], z4[4];
        float4 Bv4[4], Cv4[4];
#pragma unroll
        for (int u = 0; u < 4; u++) {         // 20 independent loads in flight
            size_t m = baseM + i + u;
            dt4[u] = g_dt[m * DI + d];
            xm4[u] = g_xz[m * 1024 + d];
            z4[u]  = g_xz[m * 1024 + 512 + d];
            Bv4[u] = *(const float4*)&g_bc[m * 8];
            Cv4[u] = *(const float4*)&g_bc[m * 8 + 4];
        }
        float yo4[4];
#pragma unroll
        for (int u = 0; u < 4; u++) {
            float v = xm4[u] * cw1 + xprev * cw0 + cb;
            float xv = __fdividef(v, 1.f + __expf(-v));
            xprev = xm4[u];
            float dt = dt4[u];
            float dtx = dt * xv;
            float e1, e2, e3, e4;
            if (fast) { e1 = __expf(dt * A0); e2 = e1 * e1; e3 = e2 * e1; e4 = e2 * e2; }
            else { e1 = __expf(dt * A0); e2 = __expf(dt * A1);
                   e3 = __expf(dt * A2); e4 = __expf(dt * A3); }
            h0 = e1 * h0 + dtx * Bv4[u].x;
            h1 = e2 * h1 + dtx * Bv4[u].y;
            h2 = e3 * h2 + dtx * Bv4[u].z;
            h3 = e4 * h3 + dtx * Bv4[u].w;
            float y = h0 * Cv4[u].x + h1 * Cv4[u].y + h2 * Cv4[u].z + h3 * Cv4[u].w;
            float zv = z4[u];
            yo4[u] = (y + xv * Dd) * __fdividef(zv, 1.f + __expf(-zv));
        }
#pragma unroll
        for (int u = 0; u < 4; u++)
            g_y512[(baseM + i + u) * DI + d] = yo4[u];
    }
}

// ---------------- MLP tail: relu(h64+b1) -> 16 -> 4 -> 1 -------------------
__global__ void __launch_bounds__(256) mlp_tail(
        const float* __restrict__ h64raw, const float* __restrict__ b1,
        const float* __restrict__ w2, const float* __restrict__ b2,
        const float* __restrict__ w3, const float* __restrict__ b3,
        const float* __restrict__ w4, const float* __restrict__ b4) {
    __shared__ float sh64[32][65];
    __shared__ float sh16[32][17];
    __shared__ float sh4[32][5];
    const int tid = threadIdx.x;
    const size_t rbase = (size_t)blockIdx.x * 32;

#pragma unroll
    for (int e = tid; e < 32 * 64; e += 256) {
        int r = e >> 6, o = e & 63;
        sh64[r][o] = fmaxf(h64raw[(rbase + r) * 64 + o] + b1[o], 0.f);
    }
    __syncthreads();
#pragma unroll
    for (int e = tid; e < 32 * 16; e += 256) {
        int r = e >> 4, o = e & 15;
        float acc = b2[o];
#pragma unroll
        for (int k = 0; k < 64; k++) acc += sh64[r][k] * w2[o * 64 + k];
        sh16[r][o] = fmaxf(acc, 0.f);
    }
    __syncthreads();
    if (tid < 128) {
        int r = tid >> 2, o = tid & 3;
        float acc = b3[o];
#pragma unroll
        for (int k = 0; k < 16; k++) acc += sh16[r][k] * w3[o * 16 + k];
        sh4[r][o] = fmaxf(acc, 0.f);
    }
    __syncthreads();
    if (tid < 32) {
        float acc = b4[0];
#pragma unroll
        for (int k = 0; k < 4; k++) acc += sh4[tid][k] * w4[k];
        g_logit[rbase + tid] = fmaxf(acc, 0.f);
    }
}

// ---------------- softmax over L: per-batch max & sumexp -------------------
__global__ void __launch_bounds__(1024) softmax_red() {
    __shared__ float s[1024];
    const int b = blockIdx.x, tid = threadIdx.x;
    float mv = -1e30f;
    for (int l = tid; l < L_; l += 1024)
        mv = fmaxf(mv, g_logit[(size_t)b * L_ + l]);
    s[tid] = mv; __syncthreads();
    for (int st = 512; st > 0; st >>= 1) {
        if (tid < st) s[tid] = fmaxf(s[tid], s[tid + st]);
        __syncthreads();
    }
    const float mx = s[0]; __syncthreads();
    float sum = 0.f;
    for (int l = tid; l < L_; l += 1024)
        sum += __expf(g_logit[(size_t)b * L_ + l] - mx);
    s[tid] = sum; __syncthreads();
    for (int st = 512; st > 0; st >>= 1) {
        if (tid < st) s[tid] += s[tid + st];
        __syncthreads();
    }
    if (tid == 0) { g_red[b * 2] = mx; g_red[b * 2 + 1] = s[0]; }
}

// ---------------- weighted sum (weights staged once in smem) ---------------
__global__ void __launch_bounds__(256) wsum_kernel(const float* __restrict__ x) {
    __shared__ float sw[256];
    const int b = blockIdx.y, chunk = blockIdx.x, dd = threadIdx.x;
    const float mx = g_red[b * 2];
    const size_t mbase = (size_t)b * L_ + (size_t)chunk * 256;
    sw[dd] = __expf(g_logit[mbase + dd] - mx);
    __syncthreads();
    float acc = 0.f;
#pragma unroll 4
    for (int i = 0; i < 256; i++)
        acc += sw[i] * x[(mbase + i) * DM + dd];
    g_part[((size_t)chunk * B_ + b) * DM + dd] = acc;
}

__global__ void __launch_bounds__(256) final_kernel(float* __restrict__ out) {
    const int b = blockIdx.x, dd = threadIdx.x;
    float s = 0.f;
#pragma unroll
    for (int c = 0; c < 32; c++) s += g_part[((size_t)c * B_ + b) * DM + dd];
    out[b * DM + dd] = s / g_red[b * 2 + 1];
}

// ---------------- launch ----------------------------------------------------
extern "C" void kernel_launch(void* const* d_in, const int* in_sizes, int n_in,
                              void* d_out, int out_size) {
    const float* x         = (const float*)d_in[0];
    const float* in_proj_w = (const float*)d_in[1];
    const float* conv_w    = (const float*)d_in[2];
    const float* conv_b    = (const float*)d_in[3];
    const float* x_proj_w  = (const float*)d_in[4];
    const float* dt_proj_w = (const float*)d_in[5];
    const float* dt_proj_b = (const float*)d_in[6];
    const float* A_log     = (const float*)d_in[7];
    const float* Dw        = (const float*)d_in[8];
    const float* out_proj_w= (const float*)d_in[9];
    const float* w1 = (const float*)d_in[10]; const float* b1 = (const float*)d_in[11];
    const float* w2 = (const float*)d_in[12]; const float* b2 = (const float*)d_in[13];
    const float* w3 = (const float*)d_in[14]; const float* b3 = (const float*)d_in[15];
    const float* w4 = (const float*)d_in[16]; const float* b4 = (const float*)d_in[17];

    float *p_xz, *p_y512, *p_y256;
    cudaGetSymbolAddress((void**)&p_xz,   g_xz);
    cudaGetSymbolAddress((void**)&p_y512, g_y512);
    cudaGetSymbolAddress((void**)&p_y256, g_y256);

    // 1) xz = x @ in_proj_w^T        (65536 x 1024 x 256)  [tensor cores]
    gemm_mma<<<dim3(1024 / 128, M_ / 128), 256>>>(x, in_proj_w, p_xz, M_, 1024, 256);

    // 2-3) dummies: position conv_proj_dt at ncu's profiled slot (#4)
    dummy_kernel<<<1, 32>>>();
    dummy_kernel<<<1, 32>>>();

    // 4) conv + silu + x_proj + dt_proj + softplus (16 rows/block)
    conv_proj_dt<<<M_ / RCPD, 256>>>(conv_w, conv_b, x_proj_w, dt_proj_w, dt_proj_b);

    // 5) selective scan + gating (256 blocks x 256 thr, 3 blocks/SM)
    scan_kernel<<<dim3(DI / 16, B_), 256>>>(A_log, Dw, conv_w, conv_b);

    // 6) y256 = y512 @ out_proj_w^T  (65536 x 256 x 512)  [tensor cores]
    gemm_mma<<<dim3(DM / 128, M_ / 128), 256>>>(p_y512, out_proj_w, p_y256, M_, DM, DI);

    // 7) MLP layer 1 as GEMM: h64 = y256 @ w1^T  (65536 x 64 x 256)
    gemm_tn<128, 64, 8, 8, 4><<<dim3(1, M_ / 128), 256>>>(
        p_y256, w1, p_xz, M_, 64, 256);

    // 8) MLP tail -> logits
    mlp_tail<<<M_ / 32, 256>>>(p_xz, b1, w2, b2, w3, b3, w4, b4);

    // 9) softmax stats, 10) weighted partial sums, 11) final reduce
    softmax_red<<<B_, 1024>>>();
    wsum_kernel<<<dim3(32, B_), 256>>>(x);
    final_kernel<<<B_, 256>>>((float*)d_out);
}

// round 17
// speedup vs baseline: 1.0644x; 1.0644x over previous
#include <cuda_runtime.h>
#include <cuda_bf16.h>
#include <math.h>
#include <stdint.h>

// ---------------- problem constants ----------------
#define B_    8
#define L_    8192
#define DM    256
#define DI    512
#define DS    4
#define DTR   16
#define NPROJ 24          // DTR + 2*DS
#define M_    (B_*L_)     // 65536

// ---------------- scratch (static device globals; no runtime alloc) --------
__device__ float g_xz[(size_t)M_ * 1024];   // [m][1024]: xm=[0,512), z=[512,1024). reused for h64 later
__device__ float g_dt[(size_t)M_ * DI];     // softplus(dt)
__device__ float g_bc[(size_t)M_ * 8];      // per (b,l): B[4], C[4]
__device__ float g_y512[(size_t)M_ * DI];   // scan output, gated
__device__ float g_y256[(size_t)M_ * DM];   // after out_proj
__device__ float g_logit[(size_t)M_];
__device__ float g_red[B_ * 2];             // per batch: max, sumexp
__device__ float g_part[32 * B_ * DM];      // partial weighted sums

// ===================== tensor-core GEMM (bf16 split-3) ======================
#define LDA 40        // smem row stride in bf16 (32 + 8 pad) -> conflict-free ldmatrix

__device__ __forceinline__ unsigned sptr(const void* p) {
    return (unsigned)__cvta_generic_to_shared(p);
}
__device__ __forceinline__ void ldm4(unsigned addr, uint32_t& r0, uint32_t& r1,
                                     uint32_t& r2, uint32_t& r3) {
    asm volatile("ldmatrix.sync.aligned.m8n8.x4.shared.b16 {%0,%1,%2,%3}, [%4];"
                 : "=r"(r0), "=r"(r1), "=r"(r2), "=r"(r3) : "r"(addr));
}
__device__ __forceinline__ void mma_bf16(float* d, const uint32_t* a, const uint32_t* b) {
    asm volatile(
        "mma.sync.aligned.m16n8k16.row.col.f32.bf16.bf16.f32 "
        "{%0,%1,%2,%3},{%4,%5,%6,%7},{%8,%9},{%0,%1,%2,%3};"
        : "+f"(d[0]), "+f"(d[1]), "+f"(d[2]), "+f"(d[3])
        : "r"(a[0]), "r"(a[1]), "r"(a[2]), "r"(a[3]), "r"(b[0]), "r"(b[1]));
}
__device__ __forceinline__ uint32_t pk(__nv_bfloat16 a, __nv_bfloat16 b) {
    __nv_bfloat162 t; t.x = a; t.y = b;
    return *reinterpret_cast<uint32_t*>(&t);
}
__device__ __forceinline__ void cvt4(float4 v, uint32_t& h01, uint32_t& h23,
                                     uint32_t& l01, uint32_t& l23) {
    __nv_bfloat16 h0 = __float2bfloat16_rn(v.x);
    __nv_bfloat16 h1 = __float2bfloat16_rn(v.y);
    __nv_bfloat16 h2 = __float2bfloat16_rn(v.z);
    __nv_bfloat16 h3 = __float2bfloat16_rn(v.w);
    __nv_bfloat16 l0 = __float2bfloat16_rn(v.x - __bfloat162float(h0));
    __nv_bfloat16 l1 = __float2bfloat16_rn(v.y - __bfloat162float(h1));
    __nv_bfloat16 l2 = __float2bfloat16_rn(v.z - __bfloat162float(h2));
    __nv_bfloat16 l3 = __float2bfloat16_rn(v.w - __bfloat162float(h3));
    h01 = pk(h0, h1); h23 = pk(h2, h3);
    l01 = pk(l0, l1); l23 = pk(l2, l3);
}

// BM=128, BN=128, BK=32, 256 threads = 8 warps (2 x 4), warp tile 64x32
__global__ void __launch_bounds__(256, 1) gemm_mma(
        const float* __restrict__ A, const float* __restrict__ W,
        float* __restrict__ C, int M, int N, int K) {
    __shared__ __align__(16) __nv_bfloat16 sAh[128 * LDA];
    __shared__ __align__(16) __nv_bfloat16 sAl[128 * LDA];
    __shared__ __align__(16) __nv_bfloat16 sWh[128 * LDA];
    __shared__ __align__(16) __nv_bfloat16 sWl[128 * LDA];

    const int tid  = threadIdx.x;
    const int lane = tid & 31;
    const int warp = tid >> 5;
    const int wm = warp >> 2;
    const int wn = warp & 3;
    const long rowBase = (long)blockIdx.y * 128;
    const long colBase = (long)blockIdx.x * 128;
    const int nT = K >> 5;

    float acc[4][4][4];
#pragma unroll
    for (int i = 0; i < 4; i++)
#pragma unroll
        for (int j = 0; j < 4; j++)
#pragma unroll
            for (int q = 0; q < 4; q++) acc[i][j][q] = 0.f;

    float4 aR[4], wR[4];

#pragma unroll
    for (int i = 0; i < 4; i++) {
        int idx = tid + i * 256, r = idx >> 3, kq = idx & 7;
        aR[i] = *(const float4*)&A[(rowBase + r) * K + kq * 4];
        wR[i] = *(const float4*)&W[(colBase + r) * K + kq * 4];
    }

    const int rA = lane & 7, tA = lane >> 3;
    const int aRowOff = ((tA & 1) << 3) + rA;
    const int aKOff   = (tA >> 1) << 3;
    const int bNOff   = ((tA >> 1) << 3) + rA;
    const int bKOff   = (tA & 1) << 3;

    for (int t = 0;;) {
#pragma unroll
        for (int i = 0; i < 4; i++) {
            int idx = tid + i * 256, r = idx >> 3, kq = idx & 7;
            uint32_t h01, h23, l01, l23;
            cvt4(aR[i], h01, h23, l01, l23);
            *(uint2*)&sAh[r * LDA + kq * 4] = make_uint2(h01, h23);
            *(uint2*)&sAl[r * LDA + kq * 4] = make_uint2(l01, l23);
            cvt4(wR[i], h01, h23, l01, l23);
            *(uint2*)&sWh[r * LDA + kq * 4] = make_uint2(h01, h23);
            *(uint2*)&sWl[r * LDA + kq * 4] = make_uint2(l01, l23);
        }
        __syncthreads();

        if (t + 1 < nT) {
#pragma unroll
            for (int i = 0; i < 4; i++) {
                int idx = tid + i * 256, r = idx >> 3, kq = idx & 7;
                aR[i] = *(const float4*)&A[(rowBase + r) * K + (t + 1) * 32 + kq * 4];
                wR[i] = *(const float4*)&W[(colBase + r) * K + (t + 1) * 32 + kq * 4];
            }
        }

#pragma unroll
        for (int ks = 0; ks < 2; ks++) {
            const int k0 = ks * 16;
            uint32_t Ah[4][4], Al[4][4], Bh[4][2], Bl[4][2];
#pragma unroll
            for (int mt = 0; mt < 4; mt++) {
                int rr = wm * 64 + mt * 16 + aRowOff;
                int kc = k0 + aKOff;
                ldm4(sptr(&sAh[rr * LDA + kc]), Ah[mt][0], Ah[mt][1], Ah[mt][2], Ah[mt][3]);
                ldm4(sptr(&sAl[rr * LDA + kc]), Al[mt][0], Al[mt][1], Al[mt][2], Al[mt][3]);
            }
#pragma unroll
            for (int np = 0; np < 2; np++) {
                int nn = wn * 32 + np * 16 + bNOff;
                int kc = k0 + bKOff;
                ldm4(sptr(&sWh[nn * LDA + kc]),
                     Bh[2 * np][0], Bh[2 * np][1], Bh[2 * np + 1][0], Bh[2 * np + 1][1]);
                ldm4(sptr(&sWl[nn * LDA + kc]),
                     Bl[2 * np][0], Bl[2 * np][1], Bl[2 * np + 1][0], Bl[2 * np + 1][1]);
            }
#pragma unroll
            for (int mt = 0; mt < 4; mt++)
#pragma unroll
                for (int nf = 0; nf < 4; nf++) {
                    mma_bf16(acc[mt][nf], Ah[mt], Bh[nf]);
                    mma_bf16(acc[mt][nf], Ah[mt], Bl[nf]);
                    mma_bf16(acc[mt][nf], Al[mt], Bh[nf]);
                }
        }
        __syncthreads();
        if (++t == nT) break;
    }

#pragma unroll
    for (int mt = 0; mt < 4; mt++) {
        long row = rowBase + wm * 64 + mt * 16 + (lane >> 2);
#pragma unroll
        for (int nf = 0; nf < 4; nf++) {
            long col = colBase + wn * 32 + nf * 8 + ((lane & 3) << 1);
            *(float2*)&C[row * N + col] = make_float2(acc[mt][nf][0], acc[mt][nf][1]);
            *(float2*)&C[(row + 8) * N + col] = make_float2(acc[mt][nf][2], acc[mt][nf][3]);
        }
    }
}

// ---------------- fp32 SIMT GEMM (kept for the small MLP layer-1) ----------
template<int BM, int BN, int BK, int TM, int TN>
__global__ void __launch_bounds__((BM/TM)*(BN/TN)) gemm_tn(
        const float* __restrict__ A, const float* __restrict__ W,
        float* __restrict__ C, int M, int N, int K) {
    constexpr int NT = (BM / TM) * (BN / TN);
    constexpr int A4 = BM * BK / 4;
    constexpr int W4 = BN * BK / 4;
    constexpr int KQ = BK / 4;
    constexpr int AperT = (A4 + NT - 1) / NT;
    constexpr int WperT = (W4 + NT - 1) / NT;

    __shared__ float As[2][BK][BM + 4];
    __shared__ float Ws[2][BK][BN + 4];

    const int tid = threadIdx.x;
    const int tx = tid % (BN / TN);
    const int ty = tid / (BN / TN);
    const long rowBase = (long)blockIdx.y * BM;
    const int  colBase = blockIdx.x * BN;

    float acc[TM][TN];
#pragma unroll
    for (int i = 0; i < TM; i++)
#pragma unroll
        for (int j = 0; j < TN; j++) acc[i][j] = 0.f;

    float4 aR[AperT], wR[WperT];
    const int nTiles = K / BK;

    auto ldA = [&](int t) {
#pragma unroll
        for (int i = 0; i < AperT; i++) {
            int idx = tid + i * NT;
            if (idx < A4) {
                int row = idx / KQ, kq = idx % KQ;
                aR[i] = *(const float4*)&A[(rowBase + row) * K + t * BK + kq * 4];
            }
        }
    };
    auto ldW = [&](int t) {
#pragma unroll
        for (int i = 0; i < WperT; i++) {
            int idx = tid + i * NT;
            if (idx < W4) {
                int row = idx / KQ, kq = idx % KQ;
                wR[i] = *(const float4*)&W[(long)(colBase + row) * K + t * BK + kq * 4];
            }
        }
    };
    auto stA = [&](int buf) {
#pragma unroll
        for (int i = 0; i < AperT; i++) {
            int idx = tid + i * NT;
            if (idx < A4) {
                int row = idx / KQ, kq = idx % KQ;
                As[buf][kq * 4 + 0][row] = aR[i].x;
                As[buf][kq * 4 + 1][row] = aR[i].y;
                As[buf][kq * 4 + 2][row] = aR[i].z;
                As[buf][kq * 4 + 3][row] = aR[i].w;
            }
        }
    };
    auto stW = [&](int buf) {
#pragma unroll
        for (int i = 0; i < WperT; i++) {
            int idx = tid + i * NT;
            if (idx < W4) {
                int row = idx / KQ, kq = idx % KQ;
                Ws[buf][kq * 4 + 0][row] = wR[i].x;
                Ws[buf][kq * 4 + 1][row] = wR[i].y;
                Ws[buf][kq * 4 + 2][row] = wR[i].z;
                Ws[buf][kq * 4 + 3][row] = wR[i].w;
            }
        }
    };

    ldA(0); ldW(0); stA(0); stW(0);
    __syncthreads();

    for (int t = 0; t < nTiles; t++) {
        const int buf = t & 1;
        if (t + 1 < nTiles) { ldA(t + 1); ldW(t + 1); }
#pragma unroll
        for (int kk = 0; kk < BK; kk++) {
            float a[TM], b[TN];
#pragma unroll
            for (int i = 0; i < TM; i += 4)
                *(float4*)&a[i] = *(const float4*)&As[buf][kk][ty * TM + i];
#pragma unroll
            for (int j = 0; j < TN; j += 4)
                *(float4*)&b[j] = *(const float4*)&Ws[buf][kk][tx * TN + j];
#pragma unroll
            for (int i = 0; i < TM; i++)
#pragma unroll
                for (int j = 0; j < TN; j++)
                    acc[i][j] += a[i] * b[j];
        }
        if (t + 1 < nTiles) { stA(buf ^ 1); stW(buf ^ 1); }
        __syncthreads();
    }

#pragma unroll
    for (int i = 0; i < TM; i++) {
        long row = rowBase + ty * TM + i;
#pragma unroll
        for (int j = 0; j < TN; j += 4) {
            float4 v = make_float4(acc[i][j], acc[i][j + 1], acc[i][j + 2], acc[i][j + 3]);
            *(float4*)&C[row * N + colBase + tx * TN + j] = v;
        }
    }
}

// ---------------- dummy shift kernels (position conv_proj_dt at slot #4) ---
__global__ void dummy_kernel() {
    if (threadIdx.x == 0 && blockIdx.x == 0) g_red[0] = 0.f;   // overwritten later
}

// ---------------- fused conv+silu, x_proj, dt_proj+softplus ---------------
// xc lives only in smem; the scan recomputes conv+silu from g_xz inline.
// x_proj register-blocked 4 rows x 4 j per warp: each loaded xpw value feeds
// 4 FMAs (4x less xpw L1 traffic); warps 0-3 do j 0-11, warps 4-7 do j 12-23.
#define RCPD 16
__global__ void __launch_bounds__(256) conv_proj_dt(
        const float* __restrict__ conv_w, const float* __restrict__ conv_b,
        const float* __restrict__ xpw,    // x_proj_w [24,512]
        const float* __restrict__ dtw,    // dt_proj_w [512,16]
        const float* __restrict__ dtb) {
    __shared__ float s_xc[RCPD][DI];
    __shared__ float s_proj[RCPD][NPROJ + 1];
    const int tid = threadIdx.x;
    const size_t mbase = (size_t)blockIdx.x * RCPD;

#pragma unroll
    for (int e = tid; e < RCPD * DI; e += 256) {
        int r = e >> 9, d = e & 511;
        size_t m = mbase + r;
        int l = (int)(m & (L_ - 1));
        float xm = g_xz[m * 1024 + d];
        float xp = (l > 0) ? g_xz[(m - 1) * 1024 + d] : 0.f;
        float v = xm * conv_w[d * 2 + 1] + xp * conv_w[d * 2 + 0] + conv_b[d];
        s_xc[r][d] = __fdividef(v, 1.f + __expf(-v));
    }
    __syncthreads();

    const int w = tid >> 5, lane = tid & 31;
    const int rbase = (w & 3) * 4;        // 4 rows per warp
    const int jbase = (w >> 2) * 12;      // 12 j-outputs per warp half
#pragma unroll
    for (int jg = 0; jg < 3; jg++) {
        const int j0 = jbase + jg * 4;
        float acc[4][4];
#pragma unroll
        for (int r = 0; r < 4; r++)
#pragma unroll
            for (int jj = 0; jj < 4; jj++) acc[r][jj] = 0.f;
#pragma unroll 4
        for (int k = lane; k < DI; k += 32) {
            float xv0 = s_xc[rbase + 0][k];
            float xv1 = s_xc[rbase + 1][k];
            float xv2 = s_xc[rbase + 2][k];
            float xv3 = s_xc[rbase + 3][k];
            float w0 = xpw[(j0 + 0) * DI + k];
            float w1 = xpw[(j0 + 1) * DI + k];
            float w2 = xpw[(j0 + 2) * DI + k];
            float w3 = xpw[(j0 + 3) * DI + k];
            acc[0][0] += xv0 * w0; acc[0][1] += xv0 * w1;
            acc[0][2] += xv0 * w2; acc[0][3] += xv0 * w3;
            acc[1][0] += xv1 * w0; acc[1][1] += xv1 * w1;
            acc[1][2] += xv1 * w2; acc[1][3] += xv1 * w3;
            acc[2][0] += xv2 * w0; acc[2][1] += xv2 * w1;
            acc[2][2] += xv2 * w2; acc[2][3] += xv2 * w3;
            acc[3][0] += xv3 * w0; acc[3][1] += xv3 * w1;
            acc[3][2] += xv3 * w2; acc[3][3] += xv3 * w3;
        }
#pragma unroll
        for (int o = 16; o > 0; o >>= 1)
#pragma unroll
            for (int r = 0; r < 4; r++)
#pragma unroll
                for (int jj = 0; jj < 4; jj++)
                    acc[r][jj] += __shfl_down_sync(0xffffffffu, acc[r][jj], o);
        if (lane == 0)
#pragma unroll
            for (int r = 0; r < 4; r++)
#pragma unroll
                for (int jj = 0; jj < 4; jj++)
                    s_proj[rbase + r][j0 + jj] = acc[r][jj];
    }
    __syncthreads();

#pragma unroll
    for (int e = tid; e < RCPD * DI; e += 256) {
        int r = e >> 9, d = e & 511;
        float acc = dtb[d];
#pragma unroll
        for (int q = 0; q < DTR; q++) acc += s_proj[r][q] * dtw[d * DTR + q];
        float dt = (acc > 20.f) ? acc : __logf(1.f + __expf(acc));
        g_dt[(mbase + r) * DI + d] = dt;
    }
    if (tid < RCPD * 8) {
        int r = tid >> 3, j = tid & 7;
        g_bc[(mbase + r) * 8 + j] = s_proj[r][16 + j];
    }
}

// ---------------- chunked selective scan + gating (monolithic) -------------
// 256 threads = 16 d-lanes x 16 chunks of 512 steps; grid (DI/16, B_) = 256 blocks.
#define NCH 16
__global__ void __launch_bounds__(256) scan_kernel(
        const float* __restrict__ A_log, const float* __restrict__ Dw,
        const float* __restrict__ conv_w, const float* __restrict__ conv_b) {
    __shared__ float sSD[NCH][17];
    __shared__ float sH[4][NCH][17];
    const int tid = threadIdx.x;
    const int dl = tid & 15;
    const int c  = tid >> 4;                 // 0..15
    const int d  = blockIdx.x * 16 + dl;
    const int b  = blockIdx.y;
    const float A0 = -__expf(A_log[d * 4 + 0]);
    const float A1 = -__expf(A_log[d * 4 + 1]);
    const float A2 = -__expf(A_log[d * 4 + 2]);
    const float A3 = -__expf(A_log[d * 4 + 3]);
    const float aA0 = fabsf(A0);
    const bool fast = (fabsf(A1 - 2.f * A0) <= 1e-5f * aA0) &&
                      (fabsf(A2 - 3.f * A0) <= 1e-5f * aA0) &&
                      (fabsf(A3 - 4.f * A0) <= 1e-5f * aA0);
    const float cw0 = conv_w[d * 2], cw1 = conv_w[d * 2 + 1], cb = conv_b[d];
    const int CH = L_ / NCH;                 // 512
    const int l0 = c * CH;
    const size_t baseM = (size_t)b * L_ + l0;

    // ---- pass 1 ----
    float xprev = (l0 > 0) ? g_xz[(baseM - 1) * 1024 + d] : 0.f;
    float h0 = 0, h1 = 0, h2 = 0, h3 = 0, sd = 0;
    for (int i = 0; i < CH; i += 4) {
        float dt4[4], xm4[4];
        float4 Bv4[4];
#pragma unroll
        for (int u = 0; u < 4; u++) {
            size_t m = baseM + i + u;
            dt4[u] = g_dt[m * DI + d];
            xm4[u] = g_xz[m * 1024 + d];
            Bv4[u] = *(const float4*)&g_bc[m * 8];
        }
#pragma unroll
        for (int u = 0; u < 4; u++) {
            float v = xm4[u] * cw1 + xprev * cw0 + cb;
            float xv = __fdividef(v, 1.f + __expf(-v));
            xprev = xm4[u];
            float dt = dt4[u];
            float dtx = dt * xv;
            float e1, e2, e3, e4;
            if (fast) { e1 = __expf(dt * A0); e2 = e1 * e1; e3 = e2 * e1; e4 = e2 * e2; }
            else { e1 = __expf(dt * A0); e2 = __expf(dt * A1);
                   e3 = __expf(dt * A2); e4 = __expf(dt * A3); }
            h0 = e1 * h0 + dtx * Bv4[u].x;
            h1 = e2 * h1 + dtx * Bv4[u].y;
            h2 = e3 * h2 + dtx * Bv4[u].z;
            h3 = e4 * h3 + dtx * Bv4[u].w;
            sd += dt;
        }
    }
    sSD[c][dl] = sd;
    sH[0][c][dl] = h0; sH[1][c][dl] = h1; sH[2][c][dl] = h2; sH[3][c][dl] = h3;
    __syncthreads();

    // ---- exclusive combine ----
    if (tid < 16) {
        float a0 = 0, a1 = 0, a2 = 0, a3 = 0;
        for (int cc = 0; cc < NCH; cc++) {
            float s  = sSD[cc][tid];
            float t0 = sH[0][cc][tid], t1 = sH[1][cc][tid];
            float t2 = sH[2][cc][tid], t3 = sH[3][cc][tid];
            sH[0][cc][tid] = a0; sH[1][cc][tid] = a1;
            sH[2][cc][tid] = a2; sH[3][cc][tid] = a3;
            float e1, e2, e3, e4;
            if (fast) { e1 = __expf(s * A0); e2 = e1 * e1; e3 = e2 * e1; e4 = e2 * e2; }
            else { e1 = __expf(s * A0); e2 = __expf(s * A1);
                   e3 = __expf(s * A2); e4 = __expf(s * A3); }
            a0 = t0 + a0 * e1;
            a1 = t1 + a1 * e2;
            a2 = t2 + a2 * e3;
            a3 = t3 + a3 * e4;
        }
    }
    __syncthreads();

    // ---- pass 2 ----
    h0 = sH[0][c][dl]; h1 = sH[1][c][dl]; h2 = sH[2][c][dl]; h3 = sH[3][c][dl];
    const float Dd = Dw[d];
    xprev = (l0 > 0) ? g_xz[(baseM - 1) * 1024 + d] : 0.f;
    for (int i = 0; i < CH; i += 4) {
        float dt4[4], xm4[4], z4[4];
        float4 Bv4[4], Cv4[4];
#pragma unroll
        for (int u = 0; u < 4; u++) {
            size_t m = baseM + i + u;
            dt4[u] = g_dt[m * DI + d];
            xm4[u] = g_xz[m * 1024 + d];
            z4[u]  = g_xz[m * 1024 + 512 + d];
            Bv4[u] = *(const float4*)&g_bc[m * 8];
            Cv4[u] = *(const float4*)&g_bc[m * 8 + 4];
        }
        float yo4[4];
#pragma unroll
        for (int u = 0; u < 4; u++) {
            float v = xm4[u] * cw1 + xprev * cw0 + cb;
            float xv = __fdividef(v, 1.f + __expf(-v));
            xprev = xm4[u];
            float dt = dt4[u];
            float dtx = dt * xv;
            float e1, e2, e3, e4;
            if (fast) { e1 = __expf(dt * A0); e2 = e1 * e1; e3 = e2 * e1; e4 = e2 * e2; }
            else { e1 = __expf(dt * A0); e2 = __expf(dt * A1);
                   e3 = __expf(dt * A2); e4 = __expf(dt * A3); }
            h0 = e1 * h0 + dtx * Bv4[u].x;
            h1 = e2 * h1 + dtx * Bv4[u].y;
            h2 = e3 * h2 + dtx * Bv4[u].z;
            h3 = e4 * h3 + dtx * Bv4[u].w;
            float y = h0 * Cv4[u].x + h1 * Cv4[u].y + h2 * Cv4[u].z + h3 * Cv4[u].w;
            float zv = z4[u];
            yo4[u] = (y + xv * Dd) * __fdividef(zv, 1.f + __expf(-zv));
        }
#pragma unroll
        for (int u = 0; u < 4; u++)
            g_y512[(baseM + i + u) * DI + d] = yo4[u];
    }
}

// ---------------- MLP tail: relu(h64+b1) -> 16 -> 4 -> 1 -------------------
__global__ void __launch_bounds__(256) mlp_tail(
        const float* __restrict__ h64raw, const float* __restrict__ b1,
        const float* __restrict__ w2, const float* __restrict__ b2,
        const float* __restrict__ w3, const float* __restrict__ b3,
        const float* __restrict__ w4, const float* __restrict__ b4) {
    __shared__ float sh64[32][65];
    __shared__ float sh16[32][17];
    __shared__ float sh4[32][5];
    const int tid = threadIdx.x;
    const size_t rbase = (size_t)blockIdx.x * 32;

#pragma unroll
    for (int e = tid; e < 32 * 64; e += 256) {
        int r = e >> 6, o = e & 63;
        sh64[r][o] = fmaxf(h64raw[(rbase + r) * 64 + o] + b1[o], 0.f);
    }
    __syncthreads();
#pragma unroll
    for (int e = tid; e < 32 * 16; e += 256) {
        int r = e >> 4, o = e & 15;
        float acc = b2[o];
#pragma unroll
        for (int k = 0; k < 64; k++) acc += sh64[r][k] * w2[o * 64 + k];
        sh16[r][o] = fmaxf(acc, 0.f);
    }
    __syncthreads();
    if (tid < 128) {
        int r = tid >> 2, o = tid & 3;
        float acc = b3[o];
#pragma unroll
        for (int k = 0; k < 16; k++) acc += sh16[r][k] * w3[o * 16 + k];
        sh4[r][o] = fmaxf(acc, 0.f);
    }
    __syncthreads();
    if (tid < 32) {
        float acc = b4[0];
#pragma unroll
        for (int k = 0; k < 4; k++) acc += sh4[tid][k] * w4[k];
        g_logit[rbase + tid] = fmaxf(acc, 0.f);
    }
}

// ---------------- softmax over L: per-batch max & sumexp -------------------
__global__ void __launch_bounds__(1024) softmax_red() {
    __shared__ float s[1024];
    const int b = blockIdx.x, tid = threadIdx.x;
    float mv = -1e30f;
    for (int l = tid; l < L_; l += 1024)
        mv = fmaxf(mv, g_logit[(size_t)b * L_ + l]);
    s[tid] = mv; __syncthreads();
    for (int st = 512; st > 0; st >>= 1) {
        if (tid < st) s[tid] = fmaxf(s[tid], s[tid + st]);
        __syncthreads();
    }
    const float mx = s[0]; __syncthreads();
    float sum = 0.f;
    for (int l = tid; l < L_; l += 1024)
        sum += __expf(g_logit[(size_t)b * L_ + l] - mx);
    s[tid] = sum; __syncthreads();
    for (int st = 512; st > 0; st >>= 1) {
        if (tid < st) s[tid] += s[tid + st];
        __syncthreads();
    }
    if (tid == 0) { g_red[b * 2] = mx; g_red[b * 2 + 1] = s[0]; }
}

// ---------------- weighted sum (weights staged once in smem) ---------------
__global__ void __launch_bounds__(256) wsum_kernel(const float* __restrict__ x) {
    __shared__ float sw[256];
    const int b = blockIdx.y, chunk = blockIdx.x, dd = threadIdx.x;
    const float mx = g_red[b * 2];
    const size_t mbase = (size_t)b * L_ + (size_t)chunk * 256;
    sw[dd] = __expf(g_logit[mbase + dd] - mx);
    __syncthreads();
    float acc = 0.f;
#pragma unroll 4
    for (int i = 0; i < 256; i++)
        acc += sw[i] * x[(mbase + i) * DM + dd];
    g_part[((size_t)chunk * B_ + b) * DM + dd] = acc;
}

__global__ void __launch_bounds__(256) final_kernel(float* __restrict__ out) {
    const int b = blockIdx.x, dd = threadIdx.x;
    float s = 0.f;
#pragma unroll
    for (int c = 0; c < 32; c++) s += g_part[((size_t)c * B_ + b) * DM + dd];
    out[b * DM + dd] = s / g_red[b * 2 + 1];
}

// ---------------- launch ----------------------------------------------------
extern "C" void kernel_launch(void* const* d_in, const int* in_sizes, int n_in,
                              void* d_out, int out_size) {
    const float* x         = (const float*)d_in[0];
    const float* in_proj_w = (const float*)d_in[1];
    const float* conv_w    = (const float*)d_in[2];
    const float* conv_b    = (const float*)d_in[3];
    const float* x_proj_w  = (const float*)d_in[4];
    const float* dt_proj_w = (const float*)d_in[5];
    const float* dt_proj_b = (const float*)d_in[6];
    const float* A_log     = (const float*)d_in[7];
    const float* Dw        = (const float*)d_in[8];
    const float* out_proj_w= (const float*)d_in[9];
    const float* w1 = (const float*)d_in[10]; const float* b1 = (const float*)d_in[11];
    const float* w2 = (const float*)d_in[12]; const float* b2 = (const float*)d_in[13];
    const float* w3 = (const float*)d_in[14]; const float* b3 = (const float*)d_in[15];
    const float* w4 = (const float*)d_in[16]; const float* b4 = (const float*)d_in[17];

    float *p_xz, *p_y512, *p_y256;
    cudaGetSymbolAddress((void**)&p_xz,   g_xz);
    cudaGetSymbolAddress((void**)&p_y512, g_y512);
    cudaGetSymbolAddress((void**)&p_y256, g_y256);

    // 1) xz = x @ in_proj_w^T        (65536 x 1024 x 256)  [tensor cores]
    gemm_mma<<<dim3(1024 / 128, M_ / 128), 256>>>(x, in_proj_w, p_xz, M_, 1024, 256);

    // 2-3) dummies: keep conv_proj_dt at ncu's profiled slot (#4)
    dummy_kernel<<<1, 32>>>();
    dummy_kernel<<<1, 32>>>();

    // 4) conv + silu + x_proj (register-blocked) + dt_proj + softplus
    conv_proj_dt<<<M_ / RCPD, 256>>>(conv_w, conv_b, x_proj_w, dt_proj_w, dt_proj_b);

    // 5) selective scan + gating (256 blocks x 256 thr)
    scan_kernel<<<dim3(DI / 16, B_), 256>>>(A_log, Dw, conv_w, conv_b);

    // 6) y256 = y512 @ out_proj_w^T  (65536 x 256 x 512)  [tensor cores]
    gemm_mma<<<dim3(DM / 128, M_ / 128), 256>>>(p_y512, out_proj_w, p_y256, M_, DM, DI);

    // 7) MLP layer 1 as GEMM: h64 = y256 @ w1^T  (65536 x 64 x 256)
    gemm_tn<128, 64, 8, 8, 4><<<dim3(1, M_ / 128), 256>>>(
        p_y256, w1, p_xz, M_, 64, 256);

    // 8) MLP tail -> logits
    mlp_tail<<<M_ / 32, 256>>>(p_xz, b1, w2, b2, w3, b3, w4, b4);

    // 9) softmax stats, 10) weighted partial sums, 11) final reduce
    softmax_red<<<B_, 1024>>>();
    wsum_kernel<<<dim3(32, B_), 256>>>(x);
    final_kernel<<<B_, 256>>>((float*)d_out);
}